// round 3
// baseline (speedup 1.0000x reference)
#include <cuda_runtime.h>
#include <cuda_bf16.h>

#define N_NODES 100000
#define N_EDGES 1280000
#define HH 64
#define NL 5
#define N_GRAPHS 512

typedef unsigned long long ull;

// ---------------- static device scratch ----------------
__device__ __align__(16) float d_z[N_NODES * HH];
__device__ __align__(16) float d_hin[N_NODES * HH];
__device__ __align__(16) float d_h1[N_NODES * 128];
__device__ __align__(16) float d_h2[N_NODES * HH];
__device__ __align__(16) float d_tab[512 * HH];
__device__ int d_counts[N_NODES];            // statically zero; re-zeroed by fill each run
__device__ int d_rowstart[N_NODES + 1];
__device__ int d_cursor[N_NODES];
__device__ int d_csr_src[N_EDGES];
__device__ unsigned short d_code[N_EDGES];
__device__ unsigned short d_csr_code[N_EDGES];
__device__ float d_s1sum[128], d_s1sq[128];
__device__ float d_s2sum[64],  d_s2sq[64];

// ---------------- packed f32x2 helpers ----------------
__device__ __forceinline__ ull pack2(float x, float y) {
    ull r; asm("mov.b64 %0, {%1, %2};" : "=l"(r) : "f"(x), "f"(y)); return r;
}
__device__ __forceinline__ void unpack2(ull v, float &x, float &y) {
    asm("mov.b64 {%0, %1}, %2;" : "=f"(x), "=f"(y) : "l"(v));
}
__device__ __forceinline__ void fma2u(ull &d, ull a, ull b) {
    asm("fma.rn.f32x2 %0, %1, %2, %0;" : "+l"(d) : "l"(a), "l"(b));
}

// ---------------- fused setup: z0 + bond table + degree count ----------------
__global__ void __launch_bounds__(256) setup_kernel(const int* __restrict__ x,
                                                    const float* __restrict__ atom_emb,
                                                    const float* __restrict__ bond_emb,
                                                    const int* __restrict__ ei,
                                                    const int* __restrict__ ea) {
    int bb = blockIdx.x;
    if (bb < 25000) {
        int t = bb * 256 + threadIdx.x;  // N*64
        int n = t >> 6, c = t & 63;
        float s = 0.f;
#pragma unroll
        for (int a = 0; a < 9; a++) {
            int idx = __ldg(&x[n * 9 + a]);
            s += __ldg(&atom_emb[(a * 128 + idx) * HH + c]);
        }
        d_z[t] = s;
    } else if (bb < 25128) {
        int t = (bb - 25000) * 256 + threadIdx.x;  // 512*64
        int q = t >> 6, c = t & 63;
        int a0 = q >> 6, a1 = (q >> 3) & 7, a2 = q & 7;
        d_tab[t] = bond_emb[a0 * HH + c] + bond_emb[(8 + a1) * HH + c] + bond_emb[(16 + a2) * HH + c];
    } else {
        int e = (bb - 25128) * 256 + threadIdx.x;  // N_EDGES
        int a0 = ea[e * 3 + 0], a1 = ea[e * 3 + 1], a2 = ea[e * 3 + 2];
        d_code[e] = (unsigned short)((a0 << 6) | (a1 << 3) | a2);
        atomicAdd(&d_counts[ei[N_EDGES + e]], 1);
    }
}

__global__ void scan_kernel() {
    __shared__ int wsum[32];
    __shared__ int s_carry;
    int tid = threadIdx.x, lane = tid & 31, wid = tid >> 5;
    if (tid == 0) s_carry = 0;
    __syncthreads();
    for (int base = 0; base < N_NODES; base += 1024) {
        int i = base + tid;
        int v = (i < N_NODES) ? d_counts[i] : 0;
        int xv = v;
#pragma unroll
        for (int o = 1; o < 32; o <<= 1) { int y = __shfl_up_sync(0xffffffffu, xv, o); if (lane >= o) xv += y; }
        if (lane == 31) wsum[wid] = xv;
        __syncthreads();
        if (wid == 0) {
            int s = wsum[lane];
#pragma unroll
            for (int o = 1; o < 32; o <<= 1) { int y = __shfl_up_sync(0xffffffffu, s, o); if (lane >= o) s += y; }
            wsum[lane] = s;
        }
        __syncthreads();
        int warp_excl = (wid > 0) ? wsum[wid - 1] : 0;
        int excl = xv + warp_excl - v;
        int carry = s_carry;
        if (i < N_NODES) { int rs = carry + excl; d_rowstart[i] = rs; d_cursor[i] = rs; }
        __syncthreads();
        if (tid == 1023) s_carry = carry + wsum[31];
        __syncthreads();
    }
    if (threadIdx.x == 0) d_rowstart[N_NODES] = s_carry;
}

// fill CSR; trailing blocks re-zero d_counts for the NEXT execution
__global__ void fill_kernel(const int* __restrict__ ei) {
    int bb = blockIdx.x;
    if (bb < 5000) {
        int e = bb * 256 + threadIdx.x;
        int dst = ei[N_EDGES + e];
        int pos = atomicAdd(&d_cursor[dst], 1);
        d_csr_src[pos] = ei[e];
        d_csr_code[pos] = d_code[e];
    } else {
        int t = (bb - 5000) * 256 + threadIdx.x;
        if (t < N_NODES) d_counts[t] = 0;
    }
}

// ---------------- per-layer kernels ----------------
// one warp per node; block 0 zeroes this layer's stat buffers
__global__ void __launch_bounds__(256) agg_kernel() {
    if (blockIdx.x == 0) {
        int t = threadIdx.x;
        if (t < 128) { d_s1sum[t] = 0.f; d_s1sq[t] = 0.f; }
        else if (t < 192) { int c = t - 128; d_s2sum[c] = 0.f; d_s2sq[c] = 0.f; }
    }
    int wg = (blockIdx.x * blockDim.x + threadIdx.x) >> 5;
    int lane = threadIdx.x & 31;
    if (wg >= N_NODES) return;
    const float2* zr = (const float2*)(d_z + (size_t)wg * HH);
    float2 acc = __ldg(&zr[lane]);
    int rs = d_rowstart[wg], re = d_rowstart[wg + 1];
    for (int base = rs; base < re; base += 32) {
        int k = base + lane;
        int s = 0, c = 0;
        if (k < re) { s = d_csr_src[k]; c = (int)d_csr_code[k]; }
        int m = re - base; if (m > 32) m = 32;
        for (int j = 0; j < m; j++) {
            int sj = __shfl_sync(0xffffffffu, s, j);
            int cj = __shfl_sync(0xffffffffu, c, j);
            float2 zv = __ldg((const float2*)(d_z + (size_t)sj * HH) + lane);
            float2 tv = __ldg((const float2*)(d_tab + cj * HH) + lane);
            acc.x += fmaxf(zv.x + tv.x, 0.f);
            acc.y += fmaxf(zv.y + tv.y, 0.f);
        }
    }
    ((float2*)(d_hin + (size_t)wg * HH))[lane] = acc;
}

// ================= GEMM1: h1[128 tile][128] = hin @ W1 + b1, fused col-stats =================
// outer-product register tile: thread = 8 nodes x 8 cols
__global__ void __launch_bounds__(256, 2) gemm1_kernel(const float* __restrict__ W, const float* __restrict__ b) {
    extern __shared__ __align__(16) float sm[];
    float* Wsh = sm;             // [64][132]
    float* Ash = sm + 64 * 132;  // [64][132]  (k-major activations, 128 nodes + pad)
    float* bsh = Ash + 64 * 132; // [128]
    int tid = threadIdx.x;
    int nb = blockIdx.x * 128;

    for (int t = tid; t < 8192; t += 256) {
        int k = t >> 7, c = t & 127;
        Wsh[k * 132 + c] = W[t];
    }
    if (tid < 128) bsh[tid] = b[tid];
    for (int t = tid; t < 8192; t += 256) {
        int n = t >> 6, c = t & 63;
        int gn = nb + n;
        Ash[c * 132 + n] = (gn < N_NODES) ? d_hin[(size_t)gn * HH + c] : 0.f;
    }
    __syncthreads();

    int warp = tid >> 5, lane = tid & 31;
    int wr = warp >> 1, wc = warp & 1;
    int tr = lane >> 3, tc = lane & 7;
    int node0 = wr * 32 + tr * 8;
    int col0 = wc * 64 + tc * 8;

    ull acc[8][4];
    {
        float4 b0 = *(const float4*)&bsh[col0];
        float4 b1 = *(const float4*)&bsh[col0 + 4];
        ull i0 = pack2(b0.x, b0.y), i1 = pack2(b0.z, b0.w);
        ull i2 = pack2(b1.x, b1.y), i3 = pack2(b1.z, b1.w);
#pragma unroll
        for (int i = 0; i < 8; i++) { acc[i][0] = i0; acc[i][1] = i1; acc[i][2] = i2; acc[i][3] = i3; }
    }

#pragma unroll 8
    for (int k = 0; k < 64; k++) {
        float4 a0 = *(const float4*)&Ash[k * 132 + node0];
        float4 a1 = *(const float4*)&Ash[k * 132 + node0 + 4];
        float4 w0 = *(const float4*)&Wsh[k * 132 + col0];
        float4 w1 = *(const float4*)&Wsh[k * 132 + col0 + 4];
        ull wp0 = pack2(w0.x, w0.y), wp1 = pack2(w0.z, w0.w);
        ull wp2 = pack2(w1.x, w1.y), wp3 = pack2(w1.z, w1.w);
        float an[8] = {a0.x, a0.y, a0.z, a0.w, a1.x, a1.y, a1.z, a1.w};
#pragma unroll
        for (int i = 0; i < 8; i++) {
            ull ai = pack2(an[i], an[i]);
            fma2u(acc[i][0], ai, wp0);
            fma2u(acc[i][1], ai, wp1);
            fma2u(acc[i][2], ai, wp2);
            fma2u(acc[i][3], ai, wp3);
        }
    }

    // store + per-thread column stats (valid nodes only)
    float csum[8] = {0,0,0,0,0,0,0,0}, csq[8] = {0,0,0,0,0,0,0,0};
#pragma unroll
    for (int i = 0; i < 8; i++) {
        int node = nb + node0 + i;
        if (node < N_NODES) {
            *(ulonglong2*)&d_h1[(size_t)node * 128 + col0] = make_ulonglong2(acc[i][0], acc[i][1]);
            *(ulonglong2*)&d_h1[(size_t)node * 128 + col0 + 4] = make_ulonglong2(acc[i][2], acc[i][3]);
#pragma unroll
            for (int j = 0; j < 4; j++) {
                float v0, v1; unpack2(acc[i][j], v0, v1);
                csum[2 * j] += v0; csq[2 * j] += v0 * v0;
                csum[2 * j + 1] += v1; csq[2 * j + 1] += v1 * v1;
            }
        }
    }
    __syncthreads();  // done reading Wsh; reuse as reduction buffer
    int g = wr * 4 + tr;  // 0..15
#pragma unroll
    for (int c = 0; c < 8; c++) {
        Wsh[g * 264 + col0 + c] = csum[c];
        Wsh[g * 264 + 128 + col0 + c] = csq[c];
    }
    __syncthreads();
    {
        float v = 0.f;
#pragma unroll
        for (int gg = 0; gg < 16; gg++) v += Wsh[gg * 264 + tid];
        if (tid < 128) atomicAdd(&d_s1sum[tid], v);
        else atomicAdd(&d_s1sq[tid - 128], v);
    }
}

// ================= GEMM2: h2[256 tile][64] = relu(bn1(h1)) @ W2 + b2, fused stats =================
__global__ void __launch_bounds__(256, 2) gemm2_kernel(const float* __restrict__ W, const float* __restrict__ b,
                                                       const float* __restrict__ gamma, const float* __restrict__ beta) {
    extern __shared__ __align__(16) float sm[];
    float* Ash = sm;              // [32][260] per k-chunk
    float* Wsh = sm + 32 * 260;   // [32][68]
    float* scs = Wsh + 32 * 68;   // [128]
    float* shs = scs + 128;       // [128]
    float* bsh = shs + 128;       // [64]
    int tid = threadIdx.x;
    int nb = blockIdx.x * 256;

    if (tid < 128) {
        float inv = 1.0f / (float)N_NODES;
        float mu = d_s1sum[tid] * inv;
        float var = d_s1sq[tid] * inv - mu * mu;
        float r = rsqrtf(var + 1e-5f);
        float sc = gamma[tid] * r;
        scs[tid] = sc; shs[tid] = beta[tid] - mu * sc;
    }
    if (tid < 64) bsh[tid] = b[tid];

    int warp = tid >> 5, lane = tid & 31;
    int wr = warp;            // 0..7 node groups of 32
    int tr = lane >> 3, tc = lane & 7;
    int node0 = wr * 32 + tr * 8;
    int col0 = tc * 8;

    ull acc[8][4];
    __syncthreads();
    {
        float4 b0 = *(const float4*)&bsh[col0];
        float4 b1 = *(const float4*)&bsh[col0 + 4];
        ull i0 = pack2(b0.x, b0.y), i1 = pack2(b0.z, b0.w);
        ull i2 = pack2(b1.x, b1.y), i3 = pack2(b1.z, b1.w);
#pragma unroll
        for (int i = 0; i < 8; i++) { acc[i][0] = i0; acc[i][1] = i1; acc[i][2] = i2; acc[i][3] = i3; }
    }

    for (int kc = 0; kc < 4; kc++) {
        __syncthreads();
        for (int t = tid; t < 2048; t += 256) {      // W chunk [32][64]
            int k = t >> 6, c = t & 63;
            Wsh[k * 68 + c] = W[(kc * 32 + k) * 64 + c];
        }
        for (int t = tid; t < 8192; t += 256) {      // A chunk: 256 nodes x 32 k, bn+relu
            int n = t >> 5, kk = t & 31;
            int gn = nb + n;
            float v = (gn < N_NODES) ? d_h1[(size_t)gn * 128 + kc * 32 + kk] : 0.f;
            Ash[kk * 260 + n] = fmaxf(fmaf(v, scs[kc * 32 + kk], shs[kc * 32 + kk]), 0.f);
        }
        __syncthreads();
#pragma unroll 8
        for (int k = 0; k < 32; k++) {
            float4 a0 = *(const float4*)&Ash[k * 260 + node0];
            float4 a1 = *(const float4*)&Ash[k * 260 + node0 + 4];
            float4 w0 = *(const float4*)&Wsh[k * 68 + col0];
            float4 w1 = *(const float4*)&Wsh[k * 68 + col0 + 4];
            ull wp0 = pack2(w0.x, w0.y), wp1 = pack2(w0.z, w0.w);
            ull wp2 = pack2(w1.x, w1.y), wp3 = pack2(w1.z, w1.w);
            float an[8] = {a0.x, a0.y, a0.z, a0.w, a1.x, a1.y, a1.z, a1.w};
#pragma unroll
            for (int i = 0; i < 8; i++) {
                ull ai = pack2(an[i], an[i]);
                fma2u(acc[i][0], ai, wp0);
                fma2u(acc[i][1], ai, wp1);
                fma2u(acc[i][2], ai, wp2);
                fma2u(acc[i][3], ai, wp3);
            }
        }
    }

    float csum[8] = {0,0,0,0,0,0,0,0}, csq[8] = {0,0,0,0,0,0,0,0};
#pragma unroll
    for (int i = 0; i < 8; i++) {
        int node = nb + node0 + i;
        if (node < N_NODES) {
            *(ulonglong2*)&d_h2[(size_t)node * HH + col0] = make_ulonglong2(acc[i][0], acc[i][1]);
            *(ulonglong2*)&d_h2[(size_t)node * HH + col0 + 4] = make_ulonglong2(acc[i][2], acc[i][3]);
#pragma unroll
            for (int j = 0; j < 4; j++) {
                float v0, v1; unpack2(acc[i][j], v0, v1);
                csum[2 * j] += v0; csq[2 * j] += v0 * v0;
                csum[2 * j + 1] += v1; csq[2 * j + 1] += v1 * v1;
            }
        }
    }
    __syncthreads();  // reuse Ash for reduction
    int g = wr * 4 + tr;  // 0..31
#pragma unroll
    for (int c = 0; c < 8; c++) {
        Ash[g * 132 + col0 + c] = csum[c];
        Ash[g * 132 + 64 + col0 + c] = csq[c];
    }
    __syncthreads();
    if (tid < 128) {
        float v = 0.f;
#pragma unroll
        for (int gg = 0; gg < 32; gg++) v += Ash[gg * 132 + tid];
        if (tid < 64) atomicAdd(&d_s2sum[tid], v);
        else atomicAdd(&d_s2sq[tid - 64], v);
    }
}

// BN2 (+relu), write z, z_cat slice, per-graph sums
__global__ void __launch_bounds__(256) finalize_kernel(const int* __restrict__ batch, float* __restrict__ out,
                                                       const float* __restrict__ gamma, const float* __restrict__ beta,
                                                       int l, int do_relu) {
    __shared__ float sred[4 * 64];
    __shared__ int sbounds[2];
    int g = blockIdx.x;
    int tid = threadIdx.x;
    int c = tid & 63, grp = tid >> 6;
    float inv = 1.0f / (float)N_NODES;
    float mu = d_s2sum[c] * inv;
    float var = d_s2sq[c] * inv - mu * mu;
    float r = rsqrtf(var + 1e-5f);
    float sc = gamma[c] * r;
    float sh = beta[c] - mu * sc;
    if (tid == 0) {
        int lo = 0, hi = N_NODES;
        while (lo < hi) { int m = (lo + hi) >> 1; if (batch[m] < g) lo = m + 1; else hi = m; }
        sbounds[0] = lo;
        hi = N_NODES;
        while (lo < hi) { int m = (lo + hi) >> 1; if (batch[m] <= g) lo = m + 1; else hi = m; }
        sbounds[1] = lo;
    }
    __syncthreads();
    int s = sbounds[0], e = sbounds[1];
    float acc = 0.f;
    for (int i = s + grp; i < e; i += 4) {
        float v = fmaf(d_h2[(size_t)i * HH + c], sc, sh);
        if (do_relu) v = fmaxf(v, 0.f);
        d_z[(size_t)i * HH + c] = v;
        out[(size_t)i * (NL * HH) + l * HH + c] = v;
        acc += v;
    }
    sred[grp * 64 + c] = acc;
    __syncthreads();
    if (grp == 0) {
        float tot = sred[c] + sred[64 + c] + sred[128 + c] + sred[192 + c];
        out[(size_t)N_NODES * (NL * HH) + (size_t)g * (NL * HH) + l * HH + c] = tot;
    }
}

// ---------------- launch ----------------
extern "C" void kernel_launch(void* const* d_in, const int* in_sizes, int n_in,
                              void* d_out, int out_size) {
    const int*   x        = (const int*)d_in[0];
    const int*   ei       = (const int*)d_in[1];
    const int*   ea       = (const int*)d_in[2];
    const int*   batch    = (const int*)d_in[3];
    const float* atom_emb = (const float*)d_in[4];
    const float* bond_emb = (const float*)d_in[5];
    const float* W1       = (const float*)d_in[6];
    const float* b1       = (const float*)d_in[7];
    const float* gamma1   = (const float*)d_in[8];
    const float* beta1    = (const float*)d_in[9];
    const float* W2       = (const float*)d_in[10];
    const float* b2       = (const float*)d_in[11];
    const float* gbn      = (const float*)d_in[12];
    const float* bbn      = (const float*)d_in[13];
    float* out = (float*)d_out;

    const int SMEM1 = (64 * 132 * 2 + 128) * 4;                      // 68096
    const int SMEM2 = (32 * 260 + 32 * 68 + 128 + 128 + 64) * 4;     // 43264
    cudaFuncSetAttribute(gemm1_kernel, cudaFuncAttributeMaxDynamicSharedMemorySize, SMEM1);
    cudaFuncSetAttribute(gemm2_kernel, cudaFuncAttributeMaxDynamicSharedMemorySize, SMEM2);

    setup_kernel<<<30128, 256>>>(x, atom_emb, bond_emb, ei, ea);
    scan_kernel<<<1, 1024>>>();
    fill_kernel<<<5391, 256>>>(ei);

    int g1_blocks = (N_NODES + 127) / 128;   // 782
    int g2_blocks = (N_NODES + 255) / 256;   // 391
    for (int l = 0; l < NL; l++) {
        agg_kernel<<<N_NODES / 8, 256>>>();
        gemm1_kernel<<<g1_blocks, 256, SMEM1>>>(W1 + (size_t)l * 64 * 128, b1 + l * 128);
        gemm2_kernel<<<g2_blocks, 256, SMEM2>>>(W2 + (size_t)l * 128 * 64, b2 + l * 64,
                                                gamma1 + l * 128, beta1 + l * 128);
        finalize_kernel<<<N_GRAPHS, 256>>>(batch, out, gbn + l * HH, bbn + l * HH, l, (l != NL - 1) ? 1 : 0);
    }
}

// round 4
// speedup vs baseline: 1.4685x; 1.4685x over previous
#include <cuda_runtime.h>
#include <cuda_bf16.h>

#define N_NODES 100000
#define N_EDGES 1280000
#define HH 64
#define NL 5
#define N_GRAPHS 512

typedef unsigned long long ull;

// ---------------- static device scratch ----------------
__device__ __align__(16) float d_z[N_NODES * HH];
__device__ __align__(16) float d_hin[N_NODES * HH];
__device__ __align__(16) float d_h1[N_NODES * 128];
__device__ __align__(16) float d_h2[N_NODES * HH];
__device__ __align__(16) float d_tab[512 * HH];
__device__ int d_counts[N_NODES];            // statically zero; re-zeroed by fill each run
__device__ int d_rowstart[N_NODES + 1];
__device__ int d_cursor[N_NODES];
__device__ int d_csr_src[N_EDGES];
__device__ unsigned short d_code[N_EDGES];
__device__ unsigned short d_csr_code[N_EDGES];
__device__ float d_s1sum[128], d_s1sq[128];
__device__ float d_s2sum[64],  d_s2sq[64];

// ---------------- packed f32x2 helpers ----------------
__device__ __forceinline__ ull pack2(float x, float y) {
    ull r; asm("mov.b64 %0, {%1, %2};" : "=l"(r) : "f"(x), "f"(y)); return r;
}
__device__ __forceinline__ void unpack2(ull v, float &x, float &y) {
    asm("mov.b64 {%0, %1}, %2;" : "=f"(x), "=f"(y) : "l"(v));
}
__device__ __forceinline__ void fma2u(ull &d, ull a, ull b) {
    asm("fma.rn.f32x2 %0, %1, %2, %0;" : "+l"(d) : "l"(a), "l"(b));
}

// ---------------- fused setup: z0 + bond table + degree count ----------------
__global__ void __launch_bounds__(256) setup_kernel(const int* __restrict__ x,
                                                    const float* __restrict__ atom_emb,
                                                    const float* __restrict__ bond_emb,
                                                    const int* __restrict__ ei,
                                                    const int* __restrict__ ea) {
    int bb = blockIdx.x;
    if (bb < 25000) {
        int t = bb * 256 + threadIdx.x;  // N*64
        int n = t >> 6, c = t & 63;
        float s = 0.f;
#pragma unroll
        for (int a = 0; a < 9; a++) {
            int idx = __ldg(&x[n * 9 + a]);
            s += __ldg(&atom_emb[(a * 128 + idx) * HH + c]);
        }
        d_z[t] = s;
    } else if (bb < 25128) {
        int t = (bb - 25000) * 256 + threadIdx.x;  // 512*64
        int q = t >> 6, c = t & 63;
        int a0 = q >> 6, a1 = (q >> 3) & 7, a2 = q & 7;
        d_tab[t] = bond_emb[a0 * HH + c] + bond_emb[(8 + a1) * HH + c] + bond_emb[(16 + a2) * HH + c];
    } else {
        int e = (bb - 25128) * 256 + threadIdx.x;  // N_EDGES
        int a0 = ea[e * 3 + 0], a1 = ea[e * 3 + 1], a2 = ea[e * 3 + 2];
        d_code[e] = (unsigned short)((a0 << 6) | (a1 << 3) | a2);
        atomicAdd(&d_counts[ei[N_EDGES + e]], 1);
    }
}

__global__ void scan_kernel() {
    __shared__ int wsum[32];
    __shared__ int s_carry;
    int tid = threadIdx.x, lane = tid & 31, wid = tid >> 5;
    if (tid == 0) s_carry = 0;
    __syncthreads();
    for (int base = 0; base < N_NODES; base += 1024) {
        int i = base + tid;
        int v = (i < N_NODES) ? d_counts[i] : 0;
        int xv = v;
#pragma unroll
        for (int o = 1; o < 32; o <<= 1) { int y = __shfl_up_sync(0xffffffffu, xv, o); if (lane >= o) xv += y; }
        if (lane == 31) wsum[wid] = xv;
        __syncthreads();
        if (wid == 0) {
            int s = wsum[lane];
#pragma unroll
            for (int o = 1; o < 32; o <<= 1) { int y = __shfl_up_sync(0xffffffffu, s, o); if (lane >= o) s += y; }
            wsum[lane] = s;
        }
        __syncthreads();
        int warp_excl = (wid > 0) ? wsum[wid - 1] : 0;
        int excl = xv + warp_excl - v;
        int carry = s_carry;
        if (i < N_NODES) { int rs = carry + excl; d_rowstart[i] = rs; d_cursor[i] = rs; }
        __syncthreads();
        if (tid == 1023) s_carry = carry + wsum[31];
        __syncthreads();
    }
    if (threadIdx.x == 0) d_rowstart[N_NODES] = s_carry;
}

// fill CSR; trailing blocks re-zero d_counts for the NEXT execution
__global__ void fill_kernel(const int* __restrict__ ei) {
    int bb = blockIdx.x;
    if (bb < 5000) {
        int e = bb * 256 + threadIdx.x;
        int dst = ei[N_EDGES + e];
        int pos = atomicAdd(&d_cursor[dst], 1);
        d_csr_src[pos] = ei[e];
        d_csr_code[pos] = d_code[e];
    } else {
        int t = (bb - 5000) * 256 + threadIdx.x;
        if (t < N_NODES) d_counts[t] = 0;
    }
}

// ---------------- per-layer kernels ----------------
// one warp per node; block 0 zeroes this layer's stat buffers
__global__ void __launch_bounds__(256) agg_kernel() {
    if (blockIdx.x == 0) {
        int t = threadIdx.x;
        if (t < 128) { d_s1sum[t] = 0.f; d_s1sq[t] = 0.f; }
        else if (t < 192) { int c = t - 128; d_s2sum[c] = 0.f; d_s2sq[c] = 0.f; }
    }
    int wg = (blockIdx.x * blockDim.x + threadIdx.x) >> 5;
    int lane = threadIdx.x & 31;
    if (wg >= N_NODES) return;
    const float2* zr = (const float2*)(d_z + (size_t)wg * HH);
    float2 acc = __ldg(&zr[lane]);
    int rs = d_rowstart[wg], re = d_rowstart[wg + 1];
    for (int base = rs; base < re; base += 32) {
        int k = base + lane;
        int s = 0, c = 0;
        if (k < re) { s = d_csr_src[k]; c = (int)d_csr_code[k]; }
        int m = re - base; if (m > 32) m = 32;
        for (int j = 0; j < m; j++) {
            int sj = __shfl_sync(0xffffffffu, s, j);
            int cj = __shfl_sync(0xffffffffu, c, j);
            float2 zv = __ldg((const float2*)(d_z + (size_t)sj * HH) + lane);
            float2 tv = __ldg((const float2*)(d_tab + cj * HH) + lane);
            acc.x += fmaxf(zv.x + tv.x, 0.f);
            acc.y += fmaxf(zv.y + tv.y, 0.f);
        }
    }
    ((float2*)(d_hin + (size_t)wg * HH))[lane] = acc;
}

// ================= GEMM1: h1[128 tile][128] = hin @ W1 + b1, fused col-stats =================
// outer-product register tile: thread = 8 nodes x 8 cols
__global__ void __launch_bounds__(256, 2) gemm1_kernel(const float* __restrict__ W, const float* __restrict__ b) {
    extern __shared__ __align__(16) float sm[];
    float* Wsh = sm;             // [64][132]
    float* Ash = sm + 64 * 132;  // [64][132]  (k-major activations, 128 nodes + pad)
    float* bsh = Ash + 64 * 132; // [128]
    int tid = threadIdx.x;
    int nb = blockIdx.x * 128;

    for (int t = tid; t < 8192; t += 256) {
        int k = t >> 7, c = t & 127;
        Wsh[k * 132 + c] = W[t];
    }
    if (tid < 128) bsh[tid] = b[tid];
    for (int t = tid; t < 8192; t += 256) {
        int n = t >> 6, c = t & 63;
        int gn = nb + n;
        Ash[c * 132 + n] = (gn < N_NODES) ? d_hin[(size_t)gn * HH + c] : 0.f;
    }
    __syncthreads();

    int warp = tid >> 5, lane = tid & 31;
    int wr = warp >> 1, wc = warp & 1;
    int tr = lane >> 3, tc = lane & 7;
    int node0 = wr * 32 + tr * 8;
    int col0 = wc * 64 + tc * 8;

    ull acc[8][4];
    {
        float4 b0 = *(const float4*)&bsh[col0];
        float4 b1 = *(const float4*)&bsh[col0 + 4];
        ull i0 = pack2(b0.x, b0.y), i1 = pack2(b0.z, b0.w);
        ull i2 = pack2(b1.x, b1.y), i3 = pack2(b1.z, b1.w);
#pragma unroll
        for (int i = 0; i < 8; i++) { acc[i][0] = i0; acc[i][1] = i1; acc[i][2] = i2; acc[i][3] = i3; }
    }

#pragma unroll 8
    for (int k = 0; k < 64; k++) {
        float4 a0 = *(const float4*)&Ash[k * 132 + node0];
        float4 a1 = *(const float4*)&Ash[k * 132 + node0 + 4];
        float4 w0 = *(const float4*)&Wsh[k * 132 + col0];
        float4 w1 = *(const float4*)&Wsh[k * 132 + col0 + 4];
        ull wp0 = pack2(w0.x, w0.y), wp1 = pack2(w0.z, w0.w);
        ull wp2 = pack2(w1.x, w1.y), wp3 = pack2(w1.z, w1.w);
        float an[8] = {a0.x, a0.y, a0.z, a0.w, a1.x, a1.y, a1.z, a1.w};
#pragma unroll
        for (int i = 0; i < 8; i++) {
            ull ai = pack2(an[i], an[i]);
            fma2u(acc[i][0], ai, wp0);
            fma2u(acc[i][1], ai, wp1);
            fma2u(acc[i][2], ai, wp2);
            fma2u(acc[i][3], ai, wp3);
        }
    }

    // store + per-thread column stats (valid nodes only)
    float csum[8] = {0,0,0,0,0,0,0,0}, csq[8] = {0,0,0,0,0,0,0,0};
#pragma unroll
    for (int i = 0; i < 8; i++) {
        int node = nb + node0 + i;
        if (node < N_NODES) {
            *(ulonglong2*)&d_h1[(size_t)node * 128 + col0] = make_ulonglong2(acc[i][0], acc[i][1]);
            *(ulonglong2*)&d_h1[(size_t)node * 128 + col0 + 4] = make_ulonglong2(acc[i][2], acc[i][3]);
#pragma unroll
            for (int j = 0; j < 4; j++) {
                float v0, v1; unpack2(acc[i][j], v0, v1);
                csum[2 * j] += v0; csq[2 * j] += v0 * v0;
                csum[2 * j + 1] += v1; csq[2 * j + 1] += v1 * v1;
            }
        }
    }
    __syncthreads();  // done reading Wsh; reuse as reduction buffer
    int g = wr * 4 + tr;  // 0..15
#pragma unroll
    for (int c = 0; c < 8; c++) {
        Wsh[g * 264 + col0 + c] = csum[c];
        Wsh[g * 264 + 128 + col0 + c] = csq[c];
    }
    __syncthreads();
    {
        float v = 0.f;
#pragma unroll
        for (int gg = 0; gg < 16; gg++) v += Wsh[gg * 264 + tid];
        if (tid < 128) atomicAdd(&d_s1sum[tid], v);
        else atomicAdd(&d_s1sq[tid - 128], v);
    }
}

// ================= GEMM2: h2[256 tile][64] = relu(bn1(h1)) @ W2 + b2, fused stats =================
__global__ void __launch_bounds__(256, 2) gemm2_kernel(const float* __restrict__ W, const float* __restrict__ b,
                                                       const float* __restrict__ gamma, const float* __restrict__ beta) {
    extern __shared__ __align__(16) float sm[];
    float* Ash = sm;              // [32][260] per k-chunk
    float* Wsh = sm + 32 * 260;   // [32][68]
    float* scs = Wsh + 32 * 68;   // [128]
    float* shs = scs + 128;       // [128]
    float* bsh = shs + 128;       // [64]
    int tid = threadIdx.x;
    int nb = blockIdx.x * 256;

    if (tid < 128) {
        float inv = 1.0f / (float)N_NODES;
        float mu = d_s1sum[tid] * inv;
        float var = d_s1sq[tid] * inv - mu * mu;
        float r = rsqrtf(var + 1e-5f);
        float sc = gamma[tid] * r;
        scs[tid] = sc; shs[tid] = beta[tid] - mu * sc;
    }
    if (tid < 64) bsh[tid] = b[tid];

    int warp = tid >> 5, lane = tid & 31;
    int wr = warp;            // 0..7 node groups of 32
    int tr = lane >> 3, tc = lane & 7;
    int node0 = wr * 32 + tr * 8;
    int col0 = tc * 8;

    ull acc[8][4];
    __syncthreads();
    {
        float4 b0 = *(const float4*)&bsh[col0];
        float4 b1 = *(const float4*)&bsh[col0 + 4];
        ull i0 = pack2(b0.x, b0.y), i1 = pack2(b0.z, b0.w);
        ull i2 = pack2(b1.x, b1.y), i3 = pack2(b1.z, b1.w);
#pragma unroll
        for (int i = 0; i < 8; i++) { acc[i][0] = i0; acc[i][1] = i1; acc[i][2] = i2; acc[i][3] = i3; }
    }

    for (int kc = 0; kc < 4; kc++) {
        __syncthreads();
        for (int t = tid; t < 2048; t += 256) {      // W chunk [32][64]
            int k = t >> 6, c = t & 63;
            Wsh[k * 68 + c] = W[(kc * 32 + k) * 64 + c];
        }
        for (int t = tid; t < 8192; t += 256) {      // A chunk: 256 nodes x 32 k, bn+relu
            int n = t >> 5, kk = t & 31;
            int gn = nb + n;
            float v = (gn < N_NODES) ? d_h1[(size_t)gn * 128 + kc * 32 + kk] : 0.f;
            Ash[kk * 260 + n] = fmaxf(fmaf(v, scs[kc * 32 + kk], shs[kc * 32 + kk]), 0.f);
        }
        __syncthreads();
#pragma unroll 8
        for (int k = 0; k < 32; k++) {
            float4 a0 = *(const float4*)&Ash[k * 260 + node0];
            float4 a1 = *(const float4*)&Ash[k * 260 + node0 + 4];
            float4 w0 = *(const float4*)&Wsh[k * 68 + col0];
            float4 w1 = *(const float4*)&Wsh[k * 68 + col0 + 4];
            ull wp0 = pack2(w0.x, w0.y), wp1 = pack2(w0.z, w0.w);
            ull wp2 = pack2(w1.x, w1.y), wp3 = pack2(w1.z, w1.w);
            float an[8] = {a0.x, a0.y, a0.z, a0.w, a1.x, a1.y, a1.z, a1.w};
#pragma unroll
            for (int i = 0; i < 8; i++) {
                ull ai = pack2(an[i], an[i]);
                fma2u(acc[i][0], ai, wp0);
                fma2u(acc[i][1], ai, wp1);
                fma2u(acc[i][2], ai, wp2);
                fma2u(acc[i][3], ai, wp3);
            }
        }
    }

    float csum[8] = {0,0,0,0,0,0,0,0}, csq[8] = {0,0,0,0,0,0,0,0};
#pragma unroll
    for (int i = 0; i < 8; i++) {
        int node = nb + node0 + i;
        if (node < N_NODES) {
            *(ulonglong2*)&d_h2[(size_t)node * HH + col0] = make_ulonglong2(acc[i][0], acc[i][1]);
            *(ulonglong2*)&d_h2[(size_t)node * HH + col0 + 4] = make_ulonglong2(acc[i][2], acc[i][3]);
#pragma unroll
            for (int j = 0; j < 4; j++) {
                float v0, v1; unpack2(acc[i][j], v0, v1);
                csum[2 * j] += v0; csq[2 * j] += v0 * v0;
                csum[2 * j + 1] += v1; csq[2 * j + 1] += v1 * v1;
            }
        }
    }
    __syncthreads();  // reuse Ash for reduction
    int g = wr * 4 + tr;  // 0..31
#pragma unroll
    for (int c = 0; c < 8; c++) {
        Ash[g * 132 + col0 + c] = csum[c];
        Ash[g * 132 + 64 + col0 + c] = csq[c];
    }
    __syncthreads();
    if (tid < 128) {
        float v = 0.f;
#pragma unroll
        for (int gg = 0; gg < 32; gg++) v += Ash[gg * 132 + tid];
        if (tid < 64) atomicAdd(&d_s2sum[tid], v);
        else atomicAdd(&d_s2sq[tid - 64], v);
    }
}

// BN2 (+relu), write z, z_cat slice, per-graph sums
__global__ void __launch_bounds__(256) finalize_kernel(const int* __restrict__ batch, float* __restrict__ out,
                                                       const float* __restrict__ gamma, const float* __restrict__ beta,
                                                       int l, int do_relu) {
    __shared__ float sred[4 * 64];
    __shared__ int sbounds[2];
    int g = blockIdx.x;
    int tid = threadIdx.x;
    int c = tid & 63, grp = tid >> 6;
    float inv = 1.0f / (float)N_NODES;
    float mu = d_s2sum[c] * inv;
    float var = d_s2sq[c] * inv - mu * mu;
    float r = rsqrtf(var + 1e-5f);
    float sc = gamma[c] * r;
    float sh = beta[c] - mu * sc;
    if (tid == 0) {
        int lo = 0, hi = N_NODES;
        while (lo < hi) { int m = (lo + hi) >> 1; if (batch[m] < g) lo = m + 1; else hi = m; }
        sbounds[0] = lo;
        hi = N_NODES;
        while (lo < hi) { int m = (lo + hi) >> 1; if (batch[m] <= g) lo = m + 1; else hi = m; }
        sbounds[1] = lo;
    }
    __syncthreads();
    int s = sbounds[0], e = sbounds[1];
    float acc = 0.f;
    for (int i = s + grp; i < e; i += 4) {
        float v = fmaf(d_h2[(size_t)i * HH + c], sc, sh);
        if (do_relu) v = fmaxf(v, 0.f);
        d_z[(size_t)i * HH + c] = v;
        out[(size_t)i * (NL * HH) + l * HH + c] = v;
        acc += v;
    }
    sred[grp * 64 + c] = acc;
    __syncthreads();
    if (grp == 0) {
        float tot = sred[c] + sred[64 + c] + sred[128 + c] + sred[192 + c];
        out[(size_t)N_NODES * (NL * HH) + (size_t)g * (NL * HH) + l * HH + c] = tot;
    }
}

// ---------------- launch ----------------
extern "C" void kernel_launch(void* const* d_in, const int* in_sizes, int n_in,
                              void* d_out, int out_size) {
    const int*   x        = (const int*)d_in[0];
    const int*   ei       = (const int*)d_in[1];
    const int*   ea       = (const int*)d_in[2];
    const int*   batch    = (const int*)d_in[3];
    const float* atom_emb = (const float*)d_in[4];
    const float* bond_emb = (const float*)d_in[5];
    const float* W1       = (const float*)d_in[6];
    const float* b1       = (const float*)d_in[7];
    const float* gamma1   = (const float*)d_in[8];
    const float* beta1    = (const float*)d_in[9];
    const float* W2       = (const float*)d_in[10];
    const float* b2       = (const float*)d_in[11];
    const float* gbn      = (const float*)d_in[12];
    const float* bbn      = (const float*)d_in[13];
    float* out = (float*)d_out;

    const int SMEM1 = (64 * 132 * 2 + 128) * 4;                      // 68096
    const int SMEM2 = (32 * 260 + 32 * 68 + 128 + 128 + 64) * 4;     // 43264
    cudaFuncSetAttribute(gemm1_kernel, cudaFuncAttributeMaxDynamicSharedMemorySize, SMEM1);
    cudaFuncSetAttribute(gemm2_kernel, cudaFuncAttributeMaxDynamicSharedMemorySize, SMEM2);

    setup_kernel<<<30128, 256>>>(x, atom_emb, bond_emb, ei, ea);
    scan_kernel<<<1, 1024>>>();
    fill_kernel<<<5391, 256>>>(ei);

    int g1_blocks = (N_NODES + 127) / 128;   // 782
    int g2_blocks = (N_NODES + 255) / 256;   // 391
    for (int l = 0; l < NL; l++) {
        agg_kernel<<<N_NODES / 8, 256>>>();
        gemm1_kernel<<<g1_blocks, 256, SMEM1>>>(W1 + (size_t)l * 64 * 128, b1 + l * 128);
        gemm2_kernel<<<g2_blocks, 256, SMEM2>>>(W2 + (size_t)l * 128 * 64, b2 + l * 64,
                                                gamma1 + l * 128, beta1 + l * 128);
        finalize_kernel<<<N_GRAPHS, 256>>>(batch, out, gbn + l * HH, bbn + l * HH, l, (l != NL - 1) ? 1 : 0);
    }
}

// round 5
// speedup vs baseline: 1.5697x; 1.0689x over previous
#include <cuda_runtime.h>
#include <cuda_bf16.h>

#define N_NODES 100000
#define N_EDGES 1280000
#define HH 64
#define NL 5
#define N_GRAPHS 512

typedef unsigned long long ull;

// ---------------- static device scratch ----------------
__device__ __align__(16) float d_z[N_NODES * HH];
__device__ __align__(16) float d_hin[N_NODES * HH];
__device__ __align__(16) float d_h1[N_NODES * 128];
__device__ __align__(16) float d_h2[N_NODES * HH];
__device__ __align__(16) float d_tab[512 * HH];
__device__ int d_counts[N_NODES];            // statically zero; re-zeroed by fill each run
__device__ int d_rowstart[N_NODES + 1];
__device__ int d_cursor[N_NODES];
__device__ unsigned int d_csr_pack[N_EDGES]; // src | (code<<17)
__device__ unsigned short d_code[N_EDGES];
__device__ float d_s1sum[128], d_s1sq[128];
__device__ float d_s2sum[64],  d_s2sq[64];

// ---------------- packed f32x2 helpers ----------------
__device__ __forceinline__ ull pack2(float x, float y) {
    ull r; asm("mov.b64 %0, {%1, %2};" : "=l"(r) : "f"(x), "f"(y)); return r;
}
__device__ __forceinline__ void unpack2(ull v, float &x, float &y) {
    asm("mov.b64 {%0, %1}, %2;" : "=f"(x), "=f"(y) : "l"(v));
}
__device__ __forceinline__ void fma2u(ull &d, ull a, ull b) {
    asm("fma.rn.f32x2 %0, %1, %2, %0;" : "+l"(d) : "l"(a), "l"(b));
}

// ---------------- fused setup: z0 + bond table + degree count ----------------
__global__ void __launch_bounds__(256) setup_kernel(const int* __restrict__ x,
                                                    const float* __restrict__ atom_emb,
                                                    const float* __restrict__ bond_emb,
                                                    const int* __restrict__ ei,
                                                    const int* __restrict__ ea) {
    int bb = blockIdx.x;
    if (bb < 25000) {
        int t = bb * 256 + threadIdx.x;  // N*64
        int n = t >> 6, c = t & 63;
        float s = 0.f;
#pragma unroll
        for (int a = 0; a < 9; a++) {
            int idx = __ldg(&x[n * 9 + a]);
            s += __ldg(&atom_emb[(a * 128 + idx) * HH + c]);
        }
        d_z[t] = s;
    } else if (bb < 25128) {
        int t = (bb - 25000) * 256 + threadIdx.x;  // 512*64
        int q = t >> 6, c = t & 63;
        int a0 = q >> 6, a1 = (q >> 3) & 7, a2 = q & 7;
        d_tab[t] = bond_emb[a0 * HH + c] + bond_emb[(8 + a1) * HH + c] + bond_emb[(16 + a2) * HH + c];
    } else {
        int e = (bb - 25128) * 256 + threadIdx.x;  // N_EDGES
        int a0 = ea[e * 3 + 0], a1 = ea[e * 3 + 1], a2 = ea[e * 3 + 2];
        d_code[e] = (unsigned short)((a0 << 6) | (a1 << 3) | a2);
        atomicAdd(&d_counts[ei[N_EDGES + e]], 1);
    }
}

__global__ void scan_kernel() {
    __shared__ int wsum[32];
    __shared__ int s_carry;
    int tid = threadIdx.x, lane = tid & 31, wid = tid >> 5;
    if (tid == 0) s_carry = 0;
    __syncthreads();
    for (int base = 0; base < N_NODES; base += 1024) {
        int i = base + tid;
        int v = (i < N_NODES) ? d_counts[i] : 0;
        int xv = v;
#pragma unroll
        for (int o = 1; o < 32; o <<= 1) { int y = __shfl_up_sync(0xffffffffu, xv, o); if (lane >= o) xv += y; }
        if (lane == 31) wsum[wid] = xv;
        __syncthreads();
        if (wid == 0) {
            int s = wsum[lane];
#pragma unroll
            for (int o = 1; o < 32; o <<= 1) { int y = __shfl_up_sync(0xffffffffu, s, o); if (lane >= o) s += y; }
            wsum[lane] = s;
        }
        __syncthreads();
        int warp_excl = (wid > 0) ? wsum[wid - 1] : 0;
        int excl = xv + warp_excl - v;
        int carry = s_carry;
        if (i < N_NODES) { int rs = carry + excl; d_rowstart[i] = rs; d_cursor[i] = rs; }
        __syncthreads();
        if (tid == 1023) s_carry = carry + wsum[31];
        __syncthreads();
    }
    if (threadIdx.x == 0) d_rowstart[N_NODES] = s_carry;
}

// fill CSR (packed src|code<<17); trailing blocks re-zero d_counts for the NEXT execution
__global__ void fill_kernel(const int* __restrict__ ei) {
    int bb = blockIdx.x;
    if (bb < 5000) {
        int e = bb * 256 + threadIdx.x;
        int dst = ei[N_EDGES + e];
        int pos = atomicAdd(&d_cursor[dst], 1);
        d_csr_pack[pos] = (unsigned int)ei[e] | ((unsigned int)d_code[e] << 17);
    } else {
        int t = (bb - 5000) * 256 + threadIdx.x;
        if (t < N_NODES) d_counts[t] = 0;
    }
}

// ---------------- per-layer kernels ----------------
// one warp per node, 2 edges in flight (half-warps), float4 per lane
__global__ void __launch_bounds__(256) agg_kernel() {
    if (blockIdx.x == 0) {
        int t = threadIdx.x;
        if (t < 128) { d_s1sum[t] = 0.f; d_s1sq[t] = 0.f; }
        else if (t < 192) { int c = t - 128; d_s2sum[c] = 0.f; d_s2sq[c] = 0.f; }
    }
    int node = (blockIdx.x * blockDim.x + threadIdx.x) >> 5;
    int lane = threadIdx.x & 31;
    if (node >= N_NODES) return;
    int h = lane & 15, half = lane >> 4;
    float4 acc = make_float4(0.f, 0.f, 0.f, 0.f);
    int rs = d_rowstart[node], re = d_rowstart[node + 1];
    for (int base = rs; base < re; base += 32) {
        int cnt = re - base; if (cnt > 32) cnt = 32;
        unsigned int pk = 0;
        if (lane < cnt) pk = d_csr_pack[base + lane];
        int jjmax = (cnt + 1) >> 1;
        for (int jj = 0; jj < jjmax; jj++) {
            int eidx = 2 * jj + half;
            unsigned int v = __shfl_sync(0xffffffffu, pk, eidx);
            if (eidx < cnt) {
                int s = (int)(v & 0x1FFFFu);
                int c = (int)(v >> 17);
                float4 zv = __ldg((const float4*)(d_z + (size_t)s * HH) + h);
                float4 tv = __ldg((const float4*)(d_tab + c * HH) + h);
                acc.x += fmaxf(zv.x + tv.x, 0.f);
                acc.y += fmaxf(zv.y + tv.y, 0.f);
                acc.z += fmaxf(zv.z + tv.z, 0.f);
                acc.w += fmaxf(zv.w + tv.w, 0.f);
            }
        }
    }
    acc.x += __shfl_xor_sync(0xffffffffu, acc.x, 16);
    acc.y += __shfl_xor_sync(0xffffffffu, acc.y, 16);
    acc.z += __shfl_xor_sync(0xffffffffu, acc.z, 16);
    acc.w += __shfl_xor_sync(0xffffffffu, acc.w, 16);
    if (half == 0) {
        float4 zv = __ldg((const float4*)(d_z + (size_t)node * HH) + h);
        acc.x += zv.x; acc.y += zv.y; acc.z += zv.z; acc.w += zv.w;
        ((float4*)(d_hin + (size_t)node * HH))[h] = acc;
    }
}

// ================= GEMM1: h1[128 tile][128] = hin @ W1 + b1, fused col-stats =================
// outer-product register tile: thread = 8 nodes x 8 cols
__global__ void __launch_bounds__(256, 2) gemm1_kernel(const float* __restrict__ W, const float* __restrict__ b) {
    extern __shared__ __align__(16) float sm[];
    float* Wsh = sm;             // [64][132]
    float* Ash = sm + 64 * 132;  // [64][132]  (k-major activations, 128 nodes + pad)
    float* bsh = Ash + 64 * 132; // [128]
    int tid = threadIdx.x;
    int nb = blockIdx.x * 128;

    for (int t = tid; t < 8192; t += 256) {
        int k = t >> 7, c = t & 127;
        Wsh[k * 132 + c] = W[t];
    }
    if (tid < 128) bsh[tid] = b[tid];
    for (int t = tid; t < 8192; t += 256) {
        int n = t >> 6, c = t & 63;
        int gn = nb + n;
        Ash[c * 132 + n] = (gn < N_NODES) ? d_hin[(size_t)gn * HH + c] : 0.f;
    }
    __syncthreads();

    int warp = tid >> 5, lane = tid & 31;
    int wr = warp >> 1, wc = warp & 1;
    int tr = lane >> 3, tc = lane & 7;
    int node0 = wr * 32 + tr * 8;
    int col0 = wc * 64 + tc * 8;

    ull acc[8][4];
    {
        float4 b0 = *(const float4*)&bsh[col0];
        float4 b1 = *(const float4*)&bsh[col0 + 4];
        ull i0 = pack2(b0.x, b0.y), i1 = pack2(b0.z, b0.w);
        ull i2 = pack2(b1.x, b1.y), i3 = pack2(b1.z, b1.w);
#pragma unroll
        for (int i = 0; i < 8; i++) { acc[i][0] = i0; acc[i][1] = i1; acc[i][2] = i2; acc[i][3] = i3; }
    }

#pragma unroll 8
    for (int k = 0; k < 64; k++) {
        float4 a0 = *(const float4*)&Ash[k * 132 + node0];
        float4 a1 = *(const float4*)&Ash[k * 132 + node0 + 4];
        float4 w0 = *(const float4*)&Wsh[k * 132 + col0];
        float4 w1 = *(const float4*)&Wsh[k * 132 + col0 + 4];
        ull wp0 = pack2(w0.x, w0.y), wp1 = pack2(w0.z, w0.w);
        ull wp2 = pack2(w1.x, w1.y), wp3 = pack2(w1.z, w1.w);
        float an[8] = {a0.x, a0.y, a0.z, a0.w, a1.x, a1.y, a1.z, a1.w};
#pragma unroll
        for (int i = 0; i < 8; i++) {
            ull ai = pack2(an[i], an[i]);
            fma2u(acc[i][0], ai, wp0);
            fma2u(acc[i][1], ai, wp1);
            fma2u(acc[i][2], ai, wp2);
            fma2u(acc[i][3], ai, wp3);
        }
    }

    float csum[8] = {0,0,0,0,0,0,0,0}, csq[8] = {0,0,0,0,0,0,0,0};
#pragma unroll
    for (int i = 0; i < 8; i++) {
        int node = nb + node0 + i;
        if (node < N_NODES) {
            *(ulonglong2*)&d_h1[(size_t)node * 128 + col0] = make_ulonglong2(acc[i][0], acc[i][1]);
            *(ulonglong2*)&d_h1[(size_t)node * 128 + col0 + 4] = make_ulonglong2(acc[i][2], acc[i][3]);
#pragma unroll
            for (int j = 0; j < 4; j++) {
                float v0, v1; unpack2(acc[i][j], v0, v1);
                csum[2 * j] += v0; csq[2 * j] += v0 * v0;
                csum[2 * j + 1] += v1; csq[2 * j + 1] += v1 * v1;
            }
        }
    }
    __syncthreads();  // done reading Wsh; reuse as reduction buffer
    int g = wr * 4 + tr;  // 0..15
#pragma unroll
    for (int c = 0; c < 8; c++) {
        Wsh[g * 264 + col0 + c] = csum[c];
        Wsh[g * 264 + 128 + col0 + c] = csq[c];
    }
    __syncthreads();
    {
        float v = 0.f;
#pragma unroll
        for (int gg = 0; gg < 16; gg++) v += Wsh[gg * 264 + tid];
        if (tid < 128) atomicAdd(&d_s1sum[tid], v);
        else atomicAdd(&d_s1sq[tid - 128], v);
    }
}

// ================= GEMM2: h2[256 tile][64] = relu(bn1(h1)) @ W2 + b2, fused stats =================
__global__ void __launch_bounds__(256, 2) gemm2_kernel(const float* __restrict__ W, const float* __restrict__ b,
                                                       const float* __restrict__ gamma, const float* __restrict__ beta) {
    extern __shared__ __align__(16) float sm[];
    float* Ash = sm;              // [32][260] per k-chunk
    float* Wsh = sm + 32 * 260;   // [32][68]
    float* scs = Wsh + 32 * 68;   // [128]
    float* shs = scs + 128;       // [128]
    float* bsh = shs + 128;       // [64]
    int tid = threadIdx.x;
    int nb = blockIdx.x * 256;

    if (tid < 128) {
        float inv = 1.0f / (float)N_NODES;
        float mu = d_s1sum[tid] * inv;
        float var = d_s1sq[tid] * inv - mu * mu;
        float r = rsqrtf(var + 1e-5f);
        float sc = gamma[tid] * r;
        scs[tid] = sc; shs[tid] = beta[tid] - mu * sc;
    }
    if (tid < 64) bsh[tid] = b[tid];

    int warp = tid >> 5, lane = tid & 31;
    int wr = warp;
    int tr = lane >> 3, tc = lane & 7;
    int node0 = wr * 32 + tr * 8;
    int col0 = tc * 8;

    ull acc[8][4];
    __syncthreads();
    {
        float4 b0 = *(const float4*)&bsh[col0];
        float4 b1 = *(const float4*)&bsh[col0 + 4];
        ull i0 = pack2(b0.x, b0.y), i1 = pack2(b0.z, b0.w);
        ull i2 = pack2(b1.x, b1.y), i3 = pack2(b1.z, b1.w);
#pragma unroll
        for (int i = 0; i < 8; i++) { acc[i][0] = i0; acc[i][1] = i1; acc[i][2] = i2; acc[i][3] = i3; }
    }

    for (int kc = 0; kc < 4; kc++) {
        __syncthreads();
        for (int t = tid; t < 2048; t += 256) {      // W chunk [32][64]
            int k = t >> 6, c = t & 63;
            Wsh[k * 68 + c] = W[(kc * 32 + k) * 64 + c];
        }
        for (int t = tid; t < 8192; t += 256) {      // A chunk: 256 nodes x 32 k, bn+relu
            int n = t >> 5, kk = t & 31;
            int gn = nb + n;
            float v = (gn < N_NODES) ? d_h1[(size_t)gn * 128 + kc * 32 + kk] : 0.f;
            Ash[kk * 260 + n] = fmaxf(fmaf(v, scs[kc * 32 + kk], shs[kc * 32 + kk]), 0.f);
        }
        __syncthreads();
#pragma unroll 8
        for (int k = 0; k < 32; k++) {
            float4 a0 = *(const float4*)&Ash[k * 260 + node0];
            float4 a1 = *(const float4*)&Ash[k * 260 + node0 + 4];
            float4 w0 = *(const float4*)&Wsh[k * 68 + col0];
            float4 w1 = *(const float4*)&Wsh[k * 68 + col0 + 4];
            ull wp0 = pack2(w0.x, w0.y), wp1 = pack2(w0.z, w0.w);
            ull wp2 = pack2(w1.x, w1.y), wp3 = pack2(w1.z, w1.w);
            float an[8] = {a0.x, a0.y, a0.z, a0.w, a1.x, a1.y, a1.z, a1.w};
#pragma unroll
            for (int i = 0; i < 8; i++) {
                ull ai = pack2(an[i], an[i]);
                fma2u(acc[i][0], ai, wp0);
                fma2u(acc[i][1], ai, wp1);
                fma2u(acc[i][2], ai, wp2);
                fma2u(acc[i][3], ai, wp3);
            }
        }
    }

    float csum[8] = {0,0,0,0,0,0,0,0}, csq[8] = {0,0,0,0,0,0,0,0};
#pragma unroll
    for (int i = 0; i < 8; i++) {
        int node = nb + node0 + i;
        if (node < N_NODES) {
            *(ulonglong2*)&d_h2[(size_t)node * HH + col0] = make_ulonglong2(acc[i][0], acc[i][1]);
            *(ulonglong2*)&d_h2[(size_t)node * HH + col0 + 4] = make_ulonglong2(acc[i][2], acc[i][3]);
#pragma unroll
            for (int j = 0; j < 4; j++) {
                float v0, v1; unpack2(acc[i][j], v0, v1);
                csum[2 * j] += v0; csq[2 * j] += v0 * v0;
                csum[2 * j + 1] += v1; csq[2 * j + 1] += v1 * v1;
            }
        }
    }
    __syncthreads();  // reuse Ash for reduction
    int g = wr * 4 + tr;  // 0..31
#pragma unroll
    for (int c = 0; c < 8; c++) {
        Ash[g * 132 + col0 + c] = csum[c];
        Ash[g * 132 + 64 + col0 + c] = csq[c];
    }
    __syncthreads();
    if (tid < 128) {
        float v = 0.f;
#pragma unroll
        for (int gg = 0; gg < 32; gg++) v += Ash[gg * 132 + tid];
        if (tid < 64) atomicAdd(&d_s2sum[tid], v);
        else atomicAdd(&d_s2sq[tid - 64], v);
    }
}

// BN2 (+relu), write z, z_cat slice, per-graph sums
__global__ void __launch_bounds__(512) finalize_kernel(const int* __restrict__ batch, float* __restrict__ out,
                                                       const float* __restrict__ gamma, const float* __restrict__ beta,
                                                       int l, int do_relu) {
    __shared__ float sred[8 * 64];
    __shared__ int sbounds[2];
    int g = blockIdx.x;
    int tid = threadIdx.x;
    int c = tid & 63, grp = tid >> 6;
    float inv = 1.0f / (float)N_NODES;
    float mu = d_s2sum[c] * inv;
    float var = d_s2sq[c] * inv - mu * mu;
    float r = rsqrtf(var + 1e-5f);
    float sc = gamma[c] * r;
    float sh = beta[c] - mu * sc;
    if (tid == 0) {
        int lo = 0, hi = N_NODES;
        while (lo < hi) { int m = (lo + hi) >> 1; if (batch[m] < g) lo = m + 1; else hi = m; }
        sbounds[0] = lo;
        hi = N_NODES;
        while (lo < hi) { int m = (lo + hi) >> 1; if (batch[m] <= g) lo = m + 1; else hi = m; }
        sbounds[1] = lo;
    }
    __syncthreads();
    int s = sbounds[0], e = sbounds[1];
    float acc = 0.f;
    for (int i = s + grp; i < e; i += 8) {
        float v = fmaf(d_h2[(size_t)i * HH + c], sc, sh);
        if (do_relu) v = fmaxf(v, 0.f);
        d_z[(size_t)i * HH + c] = v;
        out[(size_t)i * (NL * HH) + l * HH + c] = v;
        acc += v;
    }
    sred[grp * 64 + c] = acc;
    __syncthreads();
    if (grp == 0) {
        float tot = 0.f;
#pragma unroll
        for (int gg = 0; gg < 8; gg++) tot += sred[gg * 64 + c];
        out[(size_t)N_NODES * (NL * HH) + (size_t)g * (NL * HH) + l * HH + c] = tot;
    }
}

// ---------------- launch ----------------
extern "C" void kernel_launch(void* const* d_in, const int* in_sizes, int n_in,
                              void* d_out, int out_size) {
    const int*   x        = (const int*)d_in[0];
    const int*   ei       = (const int*)d_in[1];
    const int*   ea       = (const int*)d_in[2];
    const int*   batch    = (const int*)d_in[3];
    const float* atom_emb = (const float*)d_in[4];
    const float* bond_emb = (const float*)d_in[5];
    const float* W1       = (const float*)d_in[6];
    const float* b1       = (const float*)d_in[7];
    const float* gamma1   = (const float*)d_in[8];
    const float* beta1    = (const float*)d_in[9];
    const float* W2       = (const float*)d_in[10];
    const float* b2       = (const float*)d_in[11];
    const float* gbn      = (const float*)d_in[12];
    const float* bbn      = (const float*)d_in[13];
    float* out = (float*)d_out;

    const int SMEM1 = (64 * 132 * 2 + 128) * 4;                      // 68096
    const int SMEM2 = (32 * 260 + 32 * 68 + 128 + 128 + 64) * 4;     // 43264
    cudaFuncSetAttribute(gemm1_kernel, cudaFuncAttributeMaxDynamicSharedMemorySize, SMEM1);
    cudaFuncSetAttribute(gemm2_kernel, cudaFuncAttributeMaxDynamicSharedMemorySize, SMEM2);

    setup_kernel<<<30128, 256>>>(x, atom_emb, bond_emb, ei, ea);
    scan_kernel<<<1, 1024>>>();
    fill_kernel<<<5391, 256>>>(ei);

    int g1_blocks = (N_NODES + 127) / 128;   // 782
    int g2_blocks = (N_NODES + 255) / 256;   // 391
    for (int l = 0; l < NL; l++) {
        agg_kernel<<<N_NODES / 8, 256>>>();
        gemm1_kernel<<<g1_blocks, 256, SMEM1>>>(W1 + (size_t)l * 64 * 128, b1 + l * 128);
        gemm2_kernel<<<g2_blocks, 256, SMEM2>>>(W2 + (size_t)l * 128 * 64, b2 + l * 64,
                                                gamma1 + l * 128, beta1 + l * 128);
        finalize_kernel<<<N_GRAPHS, 512>>>(batch, out, gbn + l * HH, bbn + l * HH, l, (l != NL - 1) ? 1 : 0);
    }
}